// round 2
// baseline (speedup 1.0000x reference)
#include <cuda_runtime.h>
#include <stdint.h>

// Problem constants (fixed by the reference)
#define B_     16
#define N_     4096
#define TOTAL  (B_ * N_)      // 65536 tokens
#define DIM_   1024
#define E_     64
#define T_     8

// Tiling
#define BM 128                 // tokens per tile
#define BK 32                  // k-chunk
#define NTILES ((TOTAL / BM) + T_)   // 512 + 8 = 520 (padding slack per head)
#define PERM_CAP (NTILES * BM)       // 66560

#define SX_STRIDE (BM + 4)     // 132 floats: float4-aligned, conflict-reduced

// ---------------- device scratch (no allocations allowed) ----------------
__device__ int g_counts[T_];
__device__ int g_cursors[T_];
__device__ int g_paddedOff[T_ + 1];
__device__ int g_perm[PERM_CAP];

// ---------------- aux kernels ----------------
__global__ void init_kernel() {
    int i = blockIdx.x * blockDim.x + threadIdx.x;
    if (i < T_) { g_counts[i] = 0; g_cursors[i] = 0; }
    for (int j = i; j < PERM_CAP; j += gridDim.x * blockDim.x)
        g_perm[j] = -1;
}

// NOTE: index tensor is int32 (JAX demotes int64 without x64 mode).
// The & 7 is defensive: any out-of-range value becomes a wrong answer
// (diagnosable via rel_err) instead of an illegal memory access.
__global__ void count_kernel(const int* __restrict__ idx) {
    __shared__ int s[T_];
    if (threadIdx.x < T_) s[threadIdx.x] = 0;
    __syncthreads();
    int i = blockIdx.x * blockDim.x + threadIdx.x;
    if (i < TOTAL) atomicAdd(&s[idx[i] & 7], 1);
    __syncthreads();
    if (threadIdx.x < T_) atomicAdd(&g_counts[threadIdx.x], s[threadIdx.x]);
}

__global__ void scan_kernel() {
    // single thread: 8-entry exclusive scan with per-head padding to BM
    int off = 0;
    for (int h = 0; h < T_; h++) {
        g_paddedOff[h] = off;
        int tiles = (g_counts[h] + BM - 1) / BM;
        off += tiles * BM;
    }
    g_paddedOff[T_] = off;
}

__global__ void scatter_kernel(const int* __restrict__ idx) {
    int i = blockIdx.x * blockDim.x + threadIdx.x;
    if (i < TOTAL) {
        int h = idx[i] & 7;
        int p = atomicAdd(&g_cursors[h], 1);
        g_perm[g_paddedOff[h] + p] = i;
    }
}

// ---------------- main GEMM: one tile = BM tokens of a single head ----------------
__global__ __launch_bounds__(256, 4)
void gemm_kernel(const float* __restrict__ X,      // [TOTAL, DIM]
                 const float* __restrict__ W,      // [T, DIM, E]
                 const float* __restrict__ bias,   // [T, E]
                 float* __restrict__ out)          // [TOTAL, E]
{
    const int tileBase = blockIdx.x * BM;
    const int paddedTotal = g_paddedOff[T_];
    if (tileBase >= paddedTotal) return;

    // find this tile's head (tiles never straddle heads thanks to padding)
    int head = 0;
    while (g_paddedOff[head + 1] <= tileBase) head++;

    __shared__ float sx[BK][SX_STRIDE];   // x tile, transposed: sx[k][m]
    __shared__ float sw[BK][E_];          // W tile: sw[k][e]
    __shared__ int   srow[BM];

    const int tid = threadIdx.x;

    // load token ids for this tile
    if (tid < BM) srow[tid] = g_perm[tileBase + tid];
    __syncthreads();

    // thread micro-tile mapping: 16x16 thread grid -> 8 rows x 4 cols each
    const int tx = tid & 15;          // 0..15  -> col group
    const int ty = tid >> 4;          // 0..15  -> row group
    const int row0 = ty * 8;
    const int col0 = tx * 4;

    float acc[8][4];
#pragma unroll
    for (int r = 0; r < 8; r++)
#pragma unroll
        for (int c = 0; c < 4; c++) acc[r][c] = 0.0f;

    // x-tile loader mapping: lane = k index, 8 rows per pass, 16 passes
    const int llane = tid & 31;       // k within chunk
    const int lrow  = tid >> 5;       // 0..7

    const float* Whead = W + (size_t)head * DIM_ * E_;

    for (int k0 = 0; k0 < DIM_; k0 += BK) {
        // load x tile (gather rows through perm), transposed into sx[k][m]
#pragma unroll
        for (int p = 0; p < BM / 8; p++) {
            int m = lrow + p * 8;
            int tok = srow[m];
            float v = 0.0f;
            if (tok >= 0) v = X[(size_t)tok * DIM_ + k0 + llane];
            sx[llane][m] = v;
        }
        // load W tile: sw[k][e], 2048 elems / 256 threads = 8 each
#pragma unroll
        for (int p = 0; p < (BK * E_) / 256; p++) {
            int i = tid + p * 256;
            int k = i >> 6;           // /E_
            int e = i & 63;
            sw[k][e] = Whead[(size_t)(k0 + k) * E_ + e];
        }
        __syncthreads();

#pragma unroll
        for (int k = 0; k < BK; k++) {
            float4 a0 = *reinterpret_cast<const float4*>(&sx[k][row0]);
            float4 a1 = *reinterpret_cast<const float4*>(&sx[k][row0 + 4]);
            float4 bv = *reinterpret_cast<const float4*>(&sw[k][col0]);
            float a[8] = {a0.x, a0.y, a0.z, a0.w, a1.x, a1.y, a1.z, a1.w};
            float bb[4] = {bv.x, bv.y, bv.z, bv.w};
#pragma unroll
            for (int r = 0; r < 8; r++)
#pragma unroll
                for (int c = 0; c < 4; c++)
                    acc[r][c] = fmaf(a[r], bb[c], acc[r][c]);
        }
        __syncthreads();
    }

    // epilogue: bias + scatter to dense token order
    float bb[4];
#pragma unroll
    for (int c = 0; c < 4; c++) bb[c] = bias[head * E_ + col0 + c];

#pragma unroll
    for (int r = 0; r < 8; r++) {
        int tok = srow[row0 + r];
        if (tok >= 0) {
            float4 v = make_float4(acc[r][0] + bb[0], acc[r][1] + bb[1],
                                   acc[r][2] + bb[2], acc[r][3] + bb[3]);
            *reinterpret_cast<float4*>(&out[(size_t)tok * E_ + col0]) = v;
        }
    }
}

// ---------------- launch ----------------
extern "C" void kernel_launch(void* const* d_in, const int* in_sizes, int n_in,
                              void* d_out, int out_size)
{
    const float* X    = (const float*)d_in[0];   // [B,N,DIM] fp32
    const int*   idx  = (const int*)d_in[1];     // [B,N] int32 (JAX demotes int64)
    const float* W    = (const float*)d_in[2];   // [T,DIM,E] fp32
    const float* bias = (const float*)d_in[3];   // [T,E] fp32
    float*       out  = (float*)d_out;           // [B,N,E] fp32

    init_kernel<<<260, 256>>>();
    count_kernel<<<TOTAL / 256, 256>>>(idx);
    scan_kernel<<<1, 1>>>();
    scatter_kernel<<<TOTAL / 256, 256>>>(idx);
    gemm_kernel<<<NTILES, 256>>>(X, W, bias, out);
}

// round 4
// speedup vs baseline: 2.6075x; 2.6075x over previous
#include <cuda_runtime.h>
#include <stdint.h>

// Problem constants
#define B_     16
#define N_     4096
#define TOTAL  (B_ * N_)      // 65536 tokens
#define DIM_   1024
#define E_     64
#define T_     8

#define BM 128                 // tokens per tile (M)
#define BKC 64                 // K chunk
#define NCHUNK (DIM_ / BKC)    // 16
#define NTILES ((TOTAL / BM) + T_)   // 520
#define PERM_CAP (NTILES * BM)

// smem layout (bytes). Row stride 144B (72 bf16): ldmatrix conflict-free
#define XSTRIDE 144
#define WSTRIDE 144
#define WWORDS  36                       // words per W row
#define WCHUNK_WORDS (E_ * WWORDS)       // 2304 words = 9216 B per chunk image

#define OFF_XHI  0                       // [128][72] bf16 = 18432
#define OFF_XLO  18432
#define OFF_WHI  36864                   // [64][72] bf16 = 9216
#define OFF_WLO  46080
#define OFF_SROW 55296                   // 128 ints
#define SMEM_TOTAL 55808

// ---------------- device scratch ----------------
__device__ int g_counts[T_];
__device__ int g_cursors[T_];
__device__ int g_paddedOff[T_ + 1];
__device__ int g_perm[PERM_CAP];
// Pre-split W images: [head][chunk][n=64][36 words] (hi and lo bf16 pairs)
__device__ __align__(16) uint32_t g_Whi[T_ * NCHUNK * WCHUNK_WORDS];
__device__ __align__(16) uint32_t g_Wlo[T_ * NCHUNK * WCHUNK_WORDS];

// ---------------- helpers ----------------
__device__ __forceinline__ uint32_t smem_u32(const void* p) {
    uint32_t a;
    asm("{ .reg .u64 t; cvta.to.shared.u64 t, %1; cvt.u32.u64 %0, t; }" : "=r"(a) : "l"(p));
    return a;
}

// split two fp32 (a=k even -> low half) into bf16x2 hi word + bf16x2 lo word
__device__ __forceinline__ void split2(float a, float b, uint32_t& hi, uint32_t& lo) {
    asm("cvt.rn.bf16x2.f32 %0, %1, %2;" : "=r"(hi) : "f"(b), "f"(a));
    float ha = __uint_as_float(hi << 16);
    float hb = __uint_as_float(hi & 0xffff0000u);
    float ra = a - ha, rb = b - hb;
    asm("cvt.rn.bf16x2.f32 %0, %1, %2;" : "=r"(lo) : "f"(rb), "f"(ra));
}

__device__ __forceinline__ void ldsm4(uint32_t addr, uint32_t* r) {
    asm volatile("ldmatrix.sync.aligned.m8n8.x4.shared.b16 {%0,%1,%2,%3}, [%4];"
                 : "=r"(r[0]), "=r"(r[1]), "=r"(r[2]), "=r"(r[3]) : "r"(addr));
}

__device__ __forceinline__ void mma16816(float* c, const uint32_t* a,
                                         uint32_t b0, uint32_t b1) {
    asm volatile(
        "mma.sync.aligned.m16n8k16.row.col.f32.bf16.bf16.f32 "
        "{%0,%1,%2,%3}, {%4,%5,%6,%7}, {%8,%9}, {%0,%1,%2,%3};"
        : "+f"(c[0]), "+f"(c[1]), "+f"(c[2]), "+f"(c[3])
        : "r"(a[0]), "r"(a[1]), "r"(a[2]), "r"(a[3]), "r"(b0), "r"(b1));
}

// ---------------- aux kernels ----------------
__global__ void init_kernel() {
    int i = blockIdx.x * blockDim.x + threadIdx.x;
    if (i < T_) { g_counts[i] = 0; g_cursors[i] = 0; }
    for (int j = i; j < PERM_CAP; j += gridDim.x * blockDim.x)
        g_perm[j] = -1;
}

__global__ void count_kernel(const int* __restrict__ idx) {
    __shared__ int s[T_];
    if (threadIdx.x < T_) s[threadIdx.x] = 0;
    __syncthreads();
    int i = blockIdx.x * blockDim.x + threadIdx.x;
    if (i < TOTAL) atomicAdd(&s[idx[i] & 7], 1);
    __syncthreads();
    if (threadIdx.x < T_) atomicAdd(&g_counts[threadIdx.x], s[threadIdx.x]);
}

__global__ void scan_kernel() {
    int off = 0;
    for (int h = 0; h < T_; h++) {
        g_paddedOff[h] = off;
        off += ((g_counts[h] + BM - 1) / BM) * BM;
    }
    g_paddedOff[T_] = off;
}

// block-aggregated scatter: smem ranks + 8 global atomics per block
__global__ void scatter_kernel(const int* __restrict__ idx) {
    __shared__ int scnt[T_], sbase[T_];
    int t = threadIdx.x;
    if (t < T_) scnt[t] = 0;
    __syncthreads();
    int i = blockIdx.x * blockDim.x + t;
    int h = idx[i] & 7;
    int r = atomicAdd(&scnt[h], 1);
    __syncthreads();
    if (t < T_) sbase[t] = atomicAdd(&g_cursors[t], scnt[t]);
    __syncthreads();
    g_perm[g_paddedOff[h] + sbase[h] + r] = i;
}

// Pre-split W into per-chunk [n][k] bf16 hi/lo images matching the smem layout.
// One thread per (h, c, n, kpair): 8*16*64*32 = 262144 threads.
__global__ void wprep_kernel(const float* __restrict__ W) {
    int i = blockIdx.x * blockDim.x + threadIdx.x;
    int kp = i & 31;
    int n  = (i >> 5) & 63;
    int c  = (i >> 11) & 15;
    int h  = i >> 15;
    int k  = c * BKC + 2 * kp;
    float a = W[((size_t)h * DIM_ + k) * E_ + n];
    float b = W[((size_t)h * DIM_ + k + 1) * E_ + n];
    uint32_t hi, lo;
    split2(a, b, hi, lo);
    size_t dst = ((size_t)(h * NCHUNK + c) * E_ + n) * WWORDS + kp;
    g_Whi[dst] = hi;
    g_Wlo[dst] = lo;
}

// ---------------- HMMA GEMM: tile = 128 tokens of one head ----------------
__global__ __launch_bounds__(256, 3)
void gemm_mma(const float* __restrict__ X,
              const float* __restrict__ bias,
              float* __restrict__ out)
{
    const int tileBase = blockIdx.x * BM;
    if (tileBase >= g_paddedOff[T_]) return;

    int head = 0;
    while (g_paddedOff[head + 1] <= tileBase) head++;

    extern __shared__ char sm[];
    const uint32_t sbase = smem_u32(sm);
    int* srow = (int*)(sm + OFF_SROW);

    const int tid = threadIdx.x;
    const int wid = tid >> 5;
    const int lane = tid & 31;

    if (tid < BM) srow[tid] = g_perm[tileBase + tid];
    __syncthreads();

    // ---- per-thread fragment addresses ----
    const int m0 = wid * 16;
    // A (X) ldmatrix x4: tile = lane>>3: rows m0 + (lane&7) + (tile&1)*8,
    // k-halves by tile>>1
    const uint32_t aRow = m0 + (lane & 7) + ((lane >> 3) & 1) * 8;
    const uint32_t aHiA = sbase + OFF_XHI + aRow * XSTRIDE + (lane >> 4) * 16;
    const uint32_t aLoA = aHiA + (OFF_XLO - OFF_XHI);
    // B (W) ldmatrix x4 for n-block pair p: rows n = 16p + (lane>>4)*8 + (lane&7)
    const uint32_t bN = ((lane >> 4) << 3) + (lane & 7);
    const uint32_t bHiA = sbase + OFF_WHI + bN * WSTRIDE + ((lane >> 3) & 1) * 16;
    const uint32_t bLoA = bHiA + (OFF_WLO - OFF_WHI);

    // X stager mapping: j2 = 8-float k group, rb = row base
    const int j2 = tid & 7;
    const int rb = tid >> 3;          // 0..31

    float acc[32];
#pragma unroll
    for (int i = 0; i < 32; i++) acc[i] = 0.0f;

    char* xhi = sm + OFF_XHI;
    char* xlo = sm + OFF_XLO;
    uint4* whiS = (uint4*)(sm + OFF_WHI);
    uint4* wloS = (uint4*)(sm + OFF_WLO);

    for (int chunk = 0; chunk < NCHUNK; chunk++) {
        const int k0 = chunk * BKC;

        // ---- stage X chunk: fp32 -> bf16 hi/lo, [m][k] stride 144B ----
#pragma unroll
        for (int p = 0; p < 4; p++) {
            int m = rb + 32 * p;
            int tok = srow[m];
            float4 v0 = make_float4(0.f, 0.f, 0.f, 0.f), v1 = v0;
            if (tok >= 0) {
                const float4* xp = (const float4*)(X + (size_t)tok * DIM_ + k0 + j2 * 8);
                v0 = xp[0]; v1 = xp[1];
            }
            uint32_t h0, h1, h2, h3, l0, l1, l2, l3;
            split2(v0.x, v0.y, h0, l0);
            split2(v0.z, v0.w, h1, l1);
            split2(v1.x, v1.y, h2, l2);
            split2(v1.z, v1.w, h3, l3);
            uint32_t off = (uint32_t)(m * XSTRIDE + j2 * 16);
            *(uint4*)(xhi + off) = make_uint4(h0, h1, h2, h3);
            *(uint4*)(xlo + off) = make_uint4(l0, l1, l2, l3);
        }

        // ---- stage W chunk: straight copy of pre-split image ----
        {
            const uint4* shi = (const uint4*)(g_Whi + (size_t)(head * NCHUNK + chunk) * WCHUNK_WORDS);
            const uint4* slo = (const uint4*)(g_Wlo + (size_t)(head * NCHUNK + chunk) * WCHUNK_WORDS);
#pragma unroll
            for (int i = tid; i < WCHUNK_WORDS / 4; i += 256) {
                whiS[i] = shi[i];
                wloS[i] = slo[i];
            }
        }
        __syncthreads();

        // ---- HMMA over 4 k-steps of 16 ----
#pragma unroll
        for (int ks = 0; ks < 4; ks++) {
            uint32_t ah[4], al[4];
            ldsm4(aHiA + ks * 32, ah);
            ldsm4(aLoA + ks * 32, al);
#pragma unroll
            for (int p = 0; p < 4; p++) {
                uint32_t bh[4], bl[4];
                ldsm4(bHiA + p * (16 * WSTRIDE) + ks * 32, bh);
                ldsm4(bLoA + p * (16 * WSTRIDE) + ks * 32, bl);
                float* c0 = acc + (2 * p) * 4;
                float* c1 = acc + (2 * p + 1) * 4;
                mma16816(c0, ah, bh[0], bh[1]);
                mma16816(c0, ah, bl[0], bl[1]);
                mma16816(c0, al, bh[0], bh[1]);
                mma16816(c1, ah, bh[2], bh[3]);
                mma16816(c1, ah, bl[2], bl[3]);
                mma16816(c1, al, bh[2], bh[3]);
            }
        }
        __syncthreads();   // before next chunk overwrites smem
    }

    // ---- epilogue: bias + scatter stores ----
    const float* bh = bias + head * E_;
    const int e0 = 2 * (lane & 3);
    const int r1 = m0 + (lane >> 2);
    const int tok1 = srow[r1];
    const int tok2 = srow[r1 + 8];
#pragma unroll
    for (int nb = 0; nb < 8; nb++) {
        int e = nb * 8 + e0;
        float be0 = bh[e], be1 = bh[e + 1];
        if (tok1 >= 0) {
            float2 v = make_float2(acc[nb * 4 + 0] + be0, acc[nb * 4 + 1] + be1);
            *(float2*)(out + (size_t)tok1 * E_ + e) = v;
        }
        if (tok2 >= 0) {
            float2 v = make_float2(acc[nb * 4 + 2] + be0, acc[nb * 4 + 3] + be1);
            *(float2*)(out + (size_t)tok2 * E_ + e) = v;
        }
    }
}

// ---------------- launch ----------------
extern "C" void kernel_launch(void* const* d_in, const int* in_sizes, int n_in,
                              void* d_out, int out_size)
{
    const float* X    = (const float*)d_in[0];
    const int*   idx  = (const int*)d_in[1];     // int32 (JAX demotes int64)
    const float* W    = (const float*)d_in[2];
    const float* bias = (const float*)d_in[3];
    float*       out  = (float*)d_out;

    static int attr_set = 0;
    if (!attr_set) {
        cudaFuncSetAttribute(gemm_mma, cudaFuncAttributeMaxDynamicSharedMemorySize, SMEM_TOTAL);
        attr_set = 1;
    }

    init_kernel<<<260, 256>>>();
    count_kernel<<<TOTAL / 256, 256>>>(idx);
    scan_kernel<<<1, 1>>>();
    scatter_kernel<<<TOTAL / 256, 256>>>(idx);
    wprep_kernel<<<(T_ * NCHUNK * E_ * 32) / 256, 256>>>(W);
    gemm_mma<<<NTILES, 256, SMEM_TOTAL>>>(X, bias, out);
}

// round 5
// speedup vs baseline: 4.0900x; 1.5685x over previous
#include <cuda_runtime.h>
#include <stdint.h>

// Problem constants
#define B_     16
#define N_     4096
#define TOTAL  (B_ * N_)      // 65536 tokens
#define DIM_   1024
#define E_     64
#define T_     8

#define BM 128                 // tokens per tile (M)
#define BKC 64                 // K chunk
#define NCHUNK (DIM_ / BKC)    // 16
#define NTILES ((TOTAL / BM) + T_)   // 520
#define PERM_CAP (NTILES * BM)

// smem layout (bytes). Row stride 144B (72 bf16): ldmatrix conflict-free
#define XSTRIDE 144
#define WSTRIDE 144
#define WWORDS  36                       // words per W row
#define WCHUNK_WORDS (E_ * WWORDS)       // 2304 words; hi or lo image = 9216 B
#define WIMG    9216
#define WBUF    (2 * WIMG)               // hi+lo per buffer = 18432

#define OFF_XHI  0                       // [128][72] bf16 = 18432
#define OFF_XLO  18432
#define OFF_W    36864                   // 2 x (hi+lo) = 36864
#define OFF_SROW 73728                   // 128 ints
#define SMEM_TOTAL 74240

// ---------------- device scratch ----------------
__device__ int g_counts[T_];
__device__ int g_cursors[T_];
__device__ int g_paddedOff[T_ + 1];
__device__ int g_perm[PERM_CAP];
// Pre-split W images: [head][chunk][n=64][36 words] (hi and lo bf16 pairs)
__device__ __align__(16) uint32_t g_Whi[T_ * NCHUNK * WCHUNK_WORDS];
__device__ __align__(16) uint32_t g_Wlo[T_ * NCHUNK * WCHUNK_WORDS];

// ---------------- helpers ----------------
__device__ __forceinline__ uint32_t smem_u32(const void* p) {
    uint32_t a;
    asm("{ .reg .u64 t; cvta.to.shared.u64 t, %1; cvt.u32.u64 %0, t; }" : "=r"(a) : "l"(p));
    return a;
}

__device__ __forceinline__ void split2(float a, float b, uint32_t& hi, uint32_t& lo) {
    asm("cvt.rn.bf16x2.f32 %0, %1, %2;" : "=r"(hi) : "f"(b), "f"(a));
    float ha = __uint_as_float(hi << 16);
    float hb = __uint_as_float(hi & 0xffff0000u);
    float ra = a - ha, rb = b - hb;
    asm("cvt.rn.bf16x2.f32 %0, %1, %2;" : "=r"(lo) : "f"(rb), "f"(ra));
}

__device__ __forceinline__ void ldsm4(uint32_t addr, uint32_t* r) {
    asm volatile("ldmatrix.sync.aligned.m8n8.x4.shared.b16 {%0,%1,%2,%3}, [%4];"
                 : "=r"(r[0]), "=r"(r[1]), "=r"(r[2]), "=r"(r[3]) : "r"(addr));
}

__device__ __forceinline__ void mma16816(float* c, const uint32_t* a,
                                         uint32_t b0, uint32_t b1) {
    asm volatile(
        "mma.sync.aligned.m16n8k16.row.col.f32.bf16.bf16.f32 "
        "{%0,%1,%2,%3}, {%4,%5,%6,%7}, {%8,%9}, {%0,%1,%2,%3};"
        : "+f"(c[0]), "+f"(c[1]), "+f"(c[2]), "+f"(c[3])
        : "r"(a[0]), "r"(a[1]), "r"(a[2]), "r"(a[3]), "r"(b0), "r"(b1));
}

__device__ __forceinline__ void cp_async16(uint32_t saddr, const void* gaddr) {
    asm volatile("cp.async.cg.shared.global [%0], [%1], 16;"
                 :: "r"(saddr), "l"(gaddr));
}
#define CP_COMMIT() asm volatile("cp.async.commit_group;" ::: "memory")
#define CP_WAIT0()  asm volatile("cp.async.wait_group 0;" ::: "memory")

// ---------------- aux kernels ----------------
__global__ void init_kernel() {
    int i = blockIdx.x * blockDim.x + threadIdx.x;
    if (i < T_) { g_counts[i] = 0; g_cursors[i] = 0; }
    for (int j = i; j < PERM_CAP; j += gridDim.x * blockDim.x)
        g_perm[j] = -1;
}

// warp-aggregated counting, int4-vectorized
__global__ void count_kernel(const int* __restrict__ idx) {
    __shared__ int s[T_];
    if (threadIdx.x < T_) s[threadIdx.x] = 0;
    __syncthreads();
    int i = blockIdx.x * blockDim.x + threadIdx.x;
    int4 v = ((const int4*)idx)[i];
    int lane = threadIdx.x & 31;
#pragma unroll
    for (int q = 0; q < 4; q++) {
        int h = ((q == 0) ? v.x : (q == 1) ? v.y : (q == 2) ? v.z : v.w) & 7;
        unsigned mask = __match_any_sync(0xffffffffu, h);
        if ((__ffs(mask) - 1) == lane) atomicAdd(&s[h], __popc(mask));
    }
    __syncthreads();
    if (threadIdx.x < T_) atomicAdd(&g_counts[threadIdx.x], s[threadIdx.x]);
}

__global__ void scan_kernel() {
    int off = 0;
    for (int h = 0; h < T_; h++) {
        g_paddedOff[h] = off;
        off += ((g_counts[h] + BM - 1) / BM) * BM;
    }
    g_paddedOff[T_] = off;
}

// warp-aggregated scatter
__global__ void scatter_kernel(const int* __restrict__ idx) {
    __shared__ int scnt[T_], sbase[T_];
    int t = threadIdx.x;
    int lane = t & 31;
    if (t < T_) scnt[t] = 0;
    __syncthreads();
    int i = blockIdx.x * blockDim.x + t;
    int h = idx[i] & 7;
    unsigned mask = __match_any_sync(0xffffffffu, h);
    int leader = __ffs(mask) - 1;
    int rank = __popc(mask & ((1u << lane) - 1u));
    int base = 0;
    if (lane == leader) base = atomicAdd(&scnt[h], __popc(mask));
    base = __shfl_sync(0xffffffffu, base, leader);
    int r = base + rank;
    __syncthreads();
    if (t < T_) sbase[t] = atomicAdd(&g_cursors[t], scnt[t]);
    __syncthreads();
    g_perm[g_paddedOff[h] + sbase[h] + r] = i;
}

// Pre-split W into per-chunk [n][k] bf16 hi/lo images matching the smem layout.
__global__ void wprep_kernel(const float* __restrict__ W) {
    int i = blockIdx.x * blockDim.x + threadIdx.x;
    int kp = i & 31;
    int n  = (i >> 5) & 63;
    int c  = (i >> 11) & 15;
    int h  = i >> 15;
    int k  = c * BKC + 2 * kp;
    float a = W[((size_t)h * DIM_ + k) * E_ + n];
    float b = W[((size_t)h * DIM_ + k + 1) * E_ + n];
    uint32_t hi, lo;
    split2(a, b, hi, lo);
    size_t dst = ((size_t)(h * NCHUNK + c) * E_ + n) * WWORDS + kp;
    g_Whi[dst] = hi;
    g_Wlo[dst] = lo;
}

// ---------------- pipelined HMMA GEMM ----------------
__global__ __launch_bounds__(256, 2)
void gemm_mma(const float* __restrict__ X,
              const float* __restrict__ bias,
              float* __restrict__ out)
{
    const int tileBase = blockIdx.x * BM;
    if (tileBase >= g_paddedOff[T_]) return;

    int head = 0;
    while (g_paddedOff[head + 1] <= tileBase) head++;

    extern __shared__ char sm[];
    const uint32_t sbase = smem_u32(sm);
    int* srow = (int*)(sm + OFF_SROW);

    const int tid = threadIdx.x;
    const int wid = tid >> 5;
    const int lane = tid & 31;

    if (tid < BM) srow[tid] = g_perm[tileBase + tid];
    __syncthreads();

    // ---- fragment addresses ----
    const int m0 = wid * 16;
    const uint32_t aRow = m0 + (lane & 7) + ((lane >> 3) & 1) * 8;
    const uint32_t aHiA = sbase + OFF_XHI + aRow * XSTRIDE + (lane >> 4) * 16;
    const uint32_t aLoA = aHiA + (OFF_XLO - OFF_XHI);
    const uint32_t bN = ((lane >> 4) << 3) + (lane & 7);
    const uint32_t bOffLane = bN * WSTRIDE + ((lane >> 3) & 1) * 16;

    // ---- X stager mapping + cached tokens ----
    const int j2 = tid & 7;           // 8-float k group
    const int rb = tid >> 3;          // row base 0..31
    int xtok[4];
#pragma unroll
    for (int p = 0; p < 4; p++) xtok[p] = srow[rb + 32 * p];

    // ---- W copy (cp.async) setup ----
    const uint32_t wSrcBase = (uint32_t)(head * NCHUNK) * WCHUNK_WORDS;

    float acc[32];
#pragma unroll
    for (int i = 0; i < 32; i++) acc[i] = 0.0f;

    char* xhi = sm + OFF_XHI;
    char* xlo = sm + OFF_XLO;

    float4 pf[8];

    // prologue: prefetch X chunk 0 into regs, W chunk 0 via cp.async
#pragma unroll
    for (int p = 0; p < 4; p++) {
        if (xtok[p] >= 0) {
            const float4* xp = (const float4*)(X + (size_t)xtok[p] * DIM_ + j2 * 8);
            pf[2 * p] = xp[0]; pf[2 * p + 1] = xp[1];
        } else {
            pf[2 * p] = make_float4(0.f, 0.f, 0.f, 0.f);
            pf[2 * p + 1] = pf[2 * p];
        }
    }
    {
        const uint4* shi = (const uint4*)(g_Whi + wSrcBase);
        const uint4* slo = (const uint4*)(g_Wlo + wSrcBase);
        uint32_t wd = sbase + OFF_W;
#pragma unroll
        for (int i = tid; i < WIMG / 16; i += 256) {
            cp_async16(wd + i * 16, shi + i);
            cp_async16(wd + WIMG + i * 16, slo + i);
        }
        CP_COMMIT();
    }

    for (int chunk = 0; chunk < NCHUNK; chunk++) {
        // ---- convert prefetched X regs -> smem ----
#pragma unroll
        for (int p = 0; p < 4; p++) {
            uint32_t h0, h1, h2, h3, l0, l1, l2, l3;
            float4 v0 = pf[2 * p], v1 = pf[2 * p + 1];
            split2(v0.x, v0.y, h0, l0);
            split2(v0.z, v0.w, h1, l1);
            split2(v1.x, v1.y, h2, l2);
            split2(v1.z, v1.w, h3, l3);
            uint32_t off = (uint32_t)((rb + 32 * p) * XSTRIDE + j2 * 16);
            *(uint4*)(xhi + off) = make_uint4(h0, h1, h2, h3);
            *(uint4*)(xlo + off) = make_uint4(l0, l1, l2, l3);
        }

        CP_WAIT0();            // this chunk's W copy done (own copies)
        __syncthreads();       // all STS + cp.async data visible

        // ---- issue next chunk's loads (overlap with MMA below) ----
        if (chunk + 1 < NCHUNK) {
            const int k1 = (chunk + 1) * BKC;
#pragma unroll
            for (int p = 0; p < 4; p++) {
                if (xtok[p] >= 0) {
                    const float4* xp = (const float4*)(X + (size_t)xtok[p] * DIM_ + k1 + j2 * 8);
                    pf[2 * p] = xp[0]; pf[2 * p + 1] = xp[1];
                } else {
                    pf[2 * p] = make_float4(0.f, 0.f, 0.f, 0.f);
                    pf[2 * p + 1] = pf[2 * p];
                }
            }
            const uint32_t ws = wSrcBase + (chunk + 1) * WCHUNK_WORDS;
            const uint4* shi = (const uint4*)(g_Whi + ws);
            const uint4* slo = (const uint4*)(g_Wlo + ws);
            uint32_t wd = sbase + OFF_W + ((chunk + 1) & 1) * WBUF;
#pragma unroll
            for (int i = tid; i < WIMG / 16; i += 256) {
                cp_async16(wd + i * 16, shi + i);
                cp_async16(wd + WIMG + i * 16, slo + i);
            }
            CP_COMMIT();
        }

        // ---- HMMA on current buffers ----
        const uint32_t bHiA = sbase + OFF_W + (chunk & 1) * WBUF + bOffLane;
        const uint32_t bLoA = bHiA + WIMG;
#pragma unroll
        for (int ks = 0; ks < 4; ks++) {
            uint32_t ah[4], al[4];
            ldsm4(aHiA + ks * 32, ah);
            ldsm4(aLoA + ks * 32, al);
#pragma unroll
            for (int p = 0; p < 4; p++) {
                uint32_t bh[4], bl[4];
                ldsm4(bHiA + p * (16 * WSTRIDE) + ks * 32, bh);
                ldsm4(bLoA + p * (16 * WSTRIDE) + ks * 32, bl);
                float* c0 = acc + (2 * p) * 4;
                float* c1 = acc + (2 * p + 1) * 4;
                mma16816(c0, ah, bh[0], bh[1]);
                mma16816(c0, ah, bl[0], bl[1]);
                mma16816(c0, al, bh[0], bh[1]);
                mma16816(c1, ah, bh[2], bh[3]);
                mma16816(c1, ah, bl[2], bl[3]);
                mma16816(c1, al, bh[2], bh[3]);
            }
        }
        __syncthreads();   // MMA done before next chunk's STS overwrites X buf
    }

    // ---- epilogue: bias + scatter stores ----
    const float* bh = bias + head * E_;
    const int e0 = 2 * (lane & 3);
    const int r1 = m0 + (lane >> 2);
    const int tok1 = srow[r1];
    const int tok2 = srow[r1 + 8];
#pragma unroll
    for (int nb = 0; nb < 8; nb++) {
        int e = nb * 8 + e0;
        float be0 = bh[e], be1 = bh[e + 1];
        if (tok1 >= 0) {
            float2 v = make_float2(acc[nb * 4 + 0] + be0, acc[nb * 4 + 1] + be1);
            *(float2*)(out + (size_t)tok1 * E_ + e) = v;
        }
        if (tok2 >= 0) {
            float2 v = make_float2(acc[nb * 4 + 2] + be0, acc[nb * 4 + 3] + be1);
            *(float2*)(out + (size_t)tok2 * E_ + e) = v;
        }
    }
}

// ---------------- launch ----------------
extern "C" void kernel_launch(void* const* d_in, const int* in_sizes, int n_in,
                              void* d_out, int out_size)
{
    const float* X    = (const float*)d_in[0];
    const int*   idx  = (const int*)d_in[1];     // int32 (JAX demotes int64)
    const float* W    = (const float*)d_in[2];
    const float* bias = (const float*)d_in[3];
    float*       out  = (float*)d_out;

    static int attr_set = 0;
    if (!attr_set) {
        cudaFuncSetAttribute(gemm_mma, cudaFuncAttributeMaxDynamicSharedMemorySize, SMEM_TOTAL);
        attr_set = 1;
    }

    init_kernel<<<260, 256>>>();
    wprep_kernel<<<(T_ * NCHUNK * E_ * 32) / 256, 256>>>(W);
    count_kernel<<<TOTAL / 4 / 256, 256>>>(idx);
    scan_kernel<<<1, 1>>>();
    scatter_kernel<<<TOTAL / 256, 256>>>(idx);
    gemm_mma<<<NTILES, 256, SMEM_TOTAL>>>(X, bias, out);
}